// round 9
// baseline (speedup 1.0000x reference)
#include <cuda_runtime.h>
#include <cuda_bf16.h>

// GCNet cost-volume + softargmax, algebraically collapsed.
//
//   dmin = min_disp/2, dmax = max_disp/2
//   Left channels: softmax of d-constant => uniform => out = (dmin+dmax-1)/2.
//   Right channels: per-row prefix sums of exp(feaR):
//     P[x] = prefix exp(feaR[x]), Q[x] = prefix x*exp(feaR[x])
//     valid src x in [lo, hi], hi = w-dmin, lo = max(0, w-dmax+1)
//     Sv = P[hi]-P[lo-1];  Tv = w*Sv - (Q[hi]-Q[lo-1])
//     invalid d contribute exp(0)=1: z of them, Tz arithmetic series
//     disp = (Tv+Tz)/(Sv+z)
//
// R8 conclusion: latency/launch floor; best measured config is 1 warp/row,
// 8 cols/thread, 2-warp blocks, SHFL window phase (R6, kernel 6.46us).
// This round: that config + dependency-tail trims only —
//   * tree-shaped thread-local prefixes (depth 4+1 instead of 8)
//   * 32-bit address arithmetic, hoisted bases

#define BW  256   // W
#define HH  128
#define CC  32
#define RPB 2     // rows (=warps) per block
#define NTH (RPB * 32)

__global__ __launch_bounds__(NTH)
void gcnet_softargmax_kernel(const float* __restrict__ feaR,
                             const int* __restrict__ pmin,
                             const int* __restrict__ pmax,
                             float* __restrict__ out)
{
    __shared__ float sP[RPB][BW];   // generic fallback only
    __shared__ float sQ[RPB][BW];

    const int tid  = threadIdx.x;
    const int rloc = tid >> 5;                 // warp = row within block
    const int lane = tid & 31;
    const int row  = blockIdx.x * RPB + rloc;  // 0..4095 == c*H + h
    const int w0   = lane << 3;                // first of 8 columns

    const int dmin = pmin[0] / 2;              // non-negative: trunc == floor
    const int dmax = pmax[0] / 2;

    // 2x 128-bit loads: this thread's 8 columns.
    const float* rp0 = feaR + ((unsigned)row << 8) + w0;
    const float4 va = *reinterpret_cast<const float4*>(rp0);
    const float4 vb = *reinterpret_cast<const float4*>(rp0 + 4);

    // All exps on MUFU (chip-wide MUFU demand is tiny; never binding).
    const float e0 = __expf(va.x);
    const float e1 = __expf(va.y);
    const float e2 = __expf(va.z);
    const float e3 = __expf(va.w);
    const float e4 = __expf(vb.x);
    const float e5 = __expf(vb.y);
    const float e6 = __expf(vb.z);
    const float e7 = __expf(vb.w);

    const float fw0 = (float)w0;

    // Thread-local inclusive prefixes, tree-shaped: two independent 4-deep
    // half-chains, upper half offset by the lower total at the end.
    float ce[8], cq[8];
    ce[0] = e0;             cq[0] = e0 * fw0;
    ce[1] = ce[0] + e1;     cq[1] = fmaf(e1, fw0 + 1.0f, cq[0]);
    ce[2] = ce[1] + e2;     cq[2] = fmaf(e2, fw0 + 2.0f, cq[1]);
    ce[3] = ce[2] + e3;     cq[3] = fmaf(e3, fw0 + 3.0f, cq[2]);
    float ue[4], uq[4];     // upper half, independent chain
    ue[0] = e4;             uq[0] = e4 * (fw0 + 4.0f);
    ue[1] = ue[0] + e5;     uq[1] = fmaf(e5, fw0 + 5.0f, uq[0]);
    ue[2] = ue[1] + e6;     uq[2] = fmaf(e6, fw0 + 6.0f, uq[1]);
    ue[3] = ue[2] + e7;     uq[3] = fmaf(e7, fw0 + 7.0f, uq[2]);
    #pragma unroll
    for (int k = 0; k < 4; k++) { ce[4 + k] = ce[3] + ue[k]; cq[4 + k] = cq[3] + uq[k]; }

    // Warp inclusive scan of per-thread totals (5 double-shfl steps).
    float ie = ce[7], iq = cq[7];
    #pragma unroll
    for (int off = 1; off < 32; off <<= 1) {
        float a = __shfl_up_sync(0xFFFFFFFFu, ie, off);
        float b = __shfl_up_sync(0xFFFFFFFFu, iq, off);
        if (lane >= off) { ie += a; iq += b; }
    }
    const float offe = ie - ce[7];      // exclusive prefix (exact 0 for lane 0)
    const float offq = iq - cq[7];

    // Full row-inclusive prefixes, in registers.
    float P[8], Q[8];
    #pragma unroll
    for (int k = 0; k < 8; k++) { P[k] = offe + ce[k]; Q[k] = offq + cq[k]; }

    float res[8];

    if (dmin == 0 && dmax == 64) {
        // ---- Specialized all-register path (the shapes this problem runs) ----
        // hi = w -> own register.  lo-1 = w-64 -> shfl_up by 8 lanes, same k.
        #pragma unroll
        for (int k = 0; k < 8; k++) {
            const float Pm  = __shfl_up_sync(0xFFFFFFFFu, P[k], 8);
            const float Qm  = __shfl_up_sync(0xFFFFFFFFu, Q[k], 8);
            const float Plo = (lane >= 8) ? Pm : 0.0f;
            const float Qlo = (lane >= 8) ? Qm : 0.0f;
            const float fw  = fw0 + (float)k;
            const float Sv  = P[k] - Plo;
            const float Tv  = fmaf(fw, Sv, -(Q[k] - Qlo));
            // invalid d: d in [w+1, 64) -> z = max(63-w,0), Tz = (w+64)z/2
            const float zf  = fmaxf(63.0f - fw, 0.0f);
            const float Tz  = 0.5f * (fw + 64.0f) * zf;
            res[k] = __fdividef(Tv + Tz, Sv + zf);
        }
    } else {
        // ---- Generic fallback: publish prefixes to warp-private smem row ----
        #pragma unroll
        for (int k = 0; k < 8; k++) { sP[rloc][w0 + k] = P[k]; sQ[rloc][w0 + k] = Q[k]; }
        __syncwarp();
        #pragma unroll
        for (int k = 0; k < 8; k++) {
            const int w  = w0 + k;
            const int hi = w - dmin;
            float Sv = 0.0f, Tv = 0.0f;
            if (hi >= 0) {
                int lo = w - dmax + 1;
                if (lo < 0) lo = 0;
                const float Plo = (lo > 0) ? sP[rloc][lo - 1] : 0.0f;
                const float Qlo = (lo > 0) ? sQ[rloc][lo - 1] : 0.0f;
                Sv = sP[rloc][hi] - Plo;
                Tv = fmaf((float)w, Sv, -(sQ[rloc][hi] - Qlo));
            }
            int a = (w + 1 > dmin) ? (w + 1) : dmin;
            int z = dmax - a;
            if (z < 0) z = 0;
            const float Tz = (z > 0) ? 0.5f * (float)(a + dmax - 1) * (float)z : 0.0f;
            res[k] = __fdividef(Tv + Tz, Sv + (float)z);
        }
    }

    const int c = row >> 7;
    const int h = row & 127;
    const unsigned plane = HH * BW;                       // 32768
    const unsigned base  = ((unsigned)h << 8) + w0;
    const float    lc    = 0.5f * (float)(dmin + dmax - 1);

    float* rp = out + (unsigned)(CC + c) * plane + base;  // right channels
    float* lp = out + (unsigned)c * plane + base;         // left channels
    *reinterpret_cast<float4*>(rp)     = make_float4(res[0], res[1], res[2], res[3]);
    *reinterpret_cast<float4*>(rp + 4) = make_float4(res[4], res[5], res[6], res[7]);
    *reinterpret_cast<float4*>(lp)     = make_float4(lc, lc, lc, lc);
    *reinterpret_cast<float4*>(lp + 4) = make_float4(lc, lc, lc, lc);
}

extern "C" void kernel_launch(void* const* d_in, const int* in_sizes, int n_in,
                              void* d_out, int out_size)
{
    // d_in[0] = feaL (unused — left channels are analytically constant)
    const float* feaR = (const float*)d_in[1];
    const int*   pmin = (const int*)d_in[2];
    const int*   pmax = (const int*)d_in[3];
    float*       out  = (float*)d_out;

    gcnet_softargmax_kernel<<<(CC * HH) / RPB, NTH>>>(feaR, pmin, pmax, out);
}